// round 11
// baseline (speedup 1.0000x reference)
#include <cuda_runtime.h>
#include <cuda_bf16.h>
#include <cstdint>

// ---------------------------------------------------------------------------
// IngredientPositionEncoding, fused single kernel:
//   - Blocks b < B scan batch row b's separator mask once (warp-shuffle scan),
//     write int4 meta (flat_start, cnt, s, 0) for its max_ingr rows, then
//     publish flag[b].
//   - Every block waits on the flag(s) covering its 16 output rows, then runs
//     the measured-best streaming loop (16 rows/block, 8 warps, warp handles
//     rows w and w+8, float4 loads 5-deep).
//   - Last block to finish resets flags/counter so graph replays are clean.
// ---------------------------------------------------------------------------

#define MAX_SEPS_CAP 4096       // >= L
#define MAX_OUT_ROWS 65536      // >= B*max_ingr
#define MAX_B 4096
#define RPB 16                  // output rows per block

__device__ int4 g_seg_meta[MAX_OUT_ROWS];
__device__ volatile int g_flag[MAX_B];      // zero-init at load; reset in-kernel
__device__ unsigned int g_done;             // zero-init at load; reset in-kernel
__device__ int  g_fallback_max_ingr = 256;

// ---------------------------------------------------------------------------
// Fused kernel (fast path, D % 4 == 0)
// ---------------------------------------------------------------------------
__global__ void __launch_bounds__(256)
seg_mean_fused_kernel(const float4* __restrict__ x4,
                      const float4* __restrict__ pe4,
                      const int* __restrict__ mask,
                      const int* __restrict__ max_ingr_ptr,
                      int4* __restrict__ meta,
                      float4* __restrict__ out4,
                      int D4, int OUT_ROWS, int BL)
{
    __shared__ int  sh_sep[MAX_SEPS_CAP];
    __shared__ int  sh_warp[9];
    __shared__ int4 sh_meta[RPB];

    const int max_ingr = *max_ingr_ptr;
    const int B = OUT_ROWS / max_ingr;
    const int L = BL / B;

    const int tid  = threadIdx.x;
    const int lane = tid & 31;
    const int wid  = tid >> 5;
    const int bid  = blockIdx.x;

    // ---- Phase S: scan (blocks b < B, grid-stride for generality) ---------
    for (int b = bid; b < B; b += gridDim.x) {
        const int* mrow = mask + b * L;
        const int chunk = (L + 255) / 256;
        const int beg = tid * chunk;
        const int end = min(beg + chunk, L);

        int c = 0;
        if (((chunk & 3) == 0) && ((L & 3) == 0) && (beg < end)) {
            const int4* m4 = (const int4*)(mrow + beg);
            const int n4 = (end - beg) >> 2;
            for (int i = 0; i < n4; ++i) {
                int4 v = m4[i];
                c += (v.x != 0) + (v.y != 0) + (v.z != 0) + (v.w != 0);
            }
        } else {
            for (int i = beg; i < end; ++i) c += (mrow[i] != 0);
        }

        int inc = c;
        #pragma unroll
        for (int o = 1; o < 32; o <<= 1) {
            int v = __shfl_up_sync(0xffffffffu, inc, o);
            if (lane >= o) inc += v;
        }
        if (lane == 31) sh_warp[wid] = inc;
        __syncthreads();

        if (tid == 0) {
            int acc = 0;
            #pragma unroll
            for (int w = 0; w < 8; ++w) { int t = sh_warp[w]; sh_warp[w] = acc; acc += t; }
            sh_warp[8] = acc;
        }
        __syncthreads();

        const int excl = inc - c + sh_warp[wid];
        const int nsep = sh_warp[8];

        int j = excl;
        for (int i = beg; i < end; ++i) {
            if (mrow[i] != 0) {
                if (j < MAX_SEPS_CAP) sh_sep[j] = i;
                ++j;
            }
        }
        __syncthreads();

        for (int s = tid; s < max_ingr; s += 256) {
            int start, cnt;
            if (s < nsep) {
                start = (s == 0) ? 0 : (sh_sep[s - 1] + 1);
                cnt   = sh_sep[s] - start;
            } else if (s == nsep) {
                start = (nsep == 0) ? 0 : (sh_sep[nsep - 1] + 1);
                cnt   = L - start;
            } else {
                start = 0;
                cnt   = 0;
            }
            meta[b * max_ingr + s] = make_int4(b * L + start, cnt, s, 0);
        }
        __syncthreads();

        __threadfence();                 // meta visible before flag
        if (tid == 0) g_flag[b] = 1;
        __syncthreads();
    }

    // ---- Phase W: wait for the batches covering this block's rows ---------
    const int base  = bid * RPB;
    const int nrows = (base < OUT_ROWS) ? min(RPB, OUT_ROWS - base) : 0;

    if (nrows > 0) {
        const int b0 = base / max_ingr;
        const int b1 = (base + nrows - 1) / max_ingr;
        if (tid == 0) {
            for (int b = b0; b <= b1; ++b) {
                while (g_flag[b] == 0) __nanosleep(64);
            }
        }
        __syncthreads();
        __threadfence();                 // acquire side

        if (tid < nrows) sh_meta[tid] = meta[base + tid];
        __syncthreads();

        // ---- Phase B: measured-best streaming loop (R3) --------------------
        const int w = wid;
        for (int i = w; i < nrows; i += 8) {
            const int r = base + i;
            const int4 md = sh_meta[i];
            const int start = md.x;
            const int cnt   = md.y;
            const int s     = md.z;

            const float4* __restrict__ xp = x4 + (long long)start * D4;
            const float inv = (cnt > 0) ? (1.0f / (float)cnt) : 0.0f;

            for (int c = lane; c < D4; c += 32) {
                float4 a0 = {0.f,0.f,0.f,0.f}, a1 = a0, a2 = a0, a3 = a0, a4 = a0;
                int t = 0;
                for (; t + 5 <= cnt; t += 5) {
                    float4 v0 = xp[(long long)(t + 0) * D4 + c];
                    float4 v1 = xp[(long long)(t + 1) * D4 + c];
                    float4 v2 = xp[(long long)(t + 2) * D4 + c];
                    float4 v3 = xp[(long long)(t + 3) * D4 + c];
                    float4 v4 = xp[(long long)(t + 4) * D4 + c];
                    a0.x += v0.x; a0.y += v0.y; a0.z += v0.z; a0.w += v0.w;
                    a1.x += v1.x; a1.y += v1.y; a1.z += v1.z; a1.w += v1.w;
                    a2.x += v2.x; a2.y += v2.y; a2.z += v2.z; a2.w += v2.w;
                    a3.x += v3.x; a3.y += v3.y; a3.z += v3.z; a3.w += v3.w;
                    a4.x += v4.x; a4.y += v4.y; a4.z += v4.z; a4.w += v4.w;
                }
                for (; t < cnt; ++t) {
                    float4 v = xp[(long long)t * D4 + c];
                    a0.x += v.x; a0.y += v.y; a0.z += v.z; a0.w += v.w;
                }
                float4 sum;
                sum.x = ((a0.x + a1.x) + (a2.x + a3.x)) + a4.x;
                sum.y = ((a0.y + a1.y) + (a2.y + a3.y)) + a4.y;
                sum.z = ((a0.z + a1.z) + (a2.z + a3.z)) + a4.z;
                sum.w = ((a0.w + a1.w) + (a2.w + a3.w)) + a4.w;

                float4 p = pe4[(long long)s * D4 + c];
                float4 o;
                o.x = sum.x * inv + p.x;
                o.y = sum.y * inv + p.y;
                o.z = sum.z * inv + p.z;
                o.w = sum.w * inv + p.w;
                out4[(long long)r * D4 + c] = o;
            }
        }
    }

    // ---- Phase C: cleanup (last block resets flags for next replay) -------
    __syncthreads();
    if (tid == 0) {
        __threadfence();
        unsigned int d = atomicAdd(&g_done, 1u);
        if (d == gridDim.x - 1) {
            for (int b = 0; b < B; ++b) g_flag[b] = 0;
            __threadfence();
            g_done = 0;
        }
    }
}

// ---------------------------------------------------------------------------
// Fallback path (any D): boundary kernel + scalar mean kernel.
// ---------------------------------------------------------------------------
__global__ void __launch_bounds__(256)
seg_bounds_kernel(const int* __restrict__ mask,
                  const int* __restrict__ max_ingr_ptr,
                  int BL, int OUT_ROWS,
                  int4* __restrict__ meta)
{
    const int max_ingr = *max_ingr_ptr;
    const int B = OUT_ROWS / max_ingr;
    const int L = BL / B;

    __shared__ int sh_sep[MAX_SEPS_CAP];
    __shared__ int sh_warp[9];

    const int tid  = threadIdx.x;
    const int lane = tid & 31;
    const int wid  = tid >> 5;

    for (int b = blockIdx.x; b < B; b += gridDim.x) {
        const int* mrow = mask + b * L;
        const int chunk = (L + 255) / 256;
        const int beg = tid * chunk;
        const int end = min(beg + chunk, L);

        int c = 0;
        for (int i = beg; i < end; ++i) c += (mrow[i] != 0);

        int inc = c;
        #pragma unroll
        for (int o = 1; o < 32; o <<= 1) {
            int v = __shfl_up_sync(0xffffffffu, inc, o);
            if (lane >= o) inc += v;
        }
        if (lane == 31) sh_warp[wid] = inc;
        __syncthreads();
        if (tid == 0) {
            int acc = 0;
            #pragma unroll
            for (int w = 0; w < 8; ++w) { int t = sh_warp[w]; sh_warp[w] = acc; acc += t; }
            sh_warp[8] = acc;
        }
        __syncthreads();
        const int excl = inc - c + sh_warp[wid];
        const int nsep = sh_warp[8];
        int j = excl;
        for (int i = beg; i < end; ++i) {
            if (mrow[i] != 0) { if (j < MAX_SEPS_CAP) sh_sep[j] = i; ++j; }
        }
        __syncthreads();
        for (int s = tid; s < max_ingr; s += 256) {
            int start, cnt;
            if (s < nsep) {
                start = (s == 0) ? 0 : (sh_sep[s - 1] + 1);
                cnt   = sh_sep[s] - start;
            } else if (s == nsep) {
                start = (nsep == 0) ? 0 : (sh_sep[nsep - 1] + 1);
                cnt   = L - start;
            } else { start = 0; cnt = 0; }
            meta[b * max_ingr + s] = make_int4(b * L + start, cnt, s, 0);
        }
        __syncthreads();
    }
}

__global__ void seg_mean_scalar_kernel(const float* __restrict__ x,
                                       const float* __restrict__ pe,
                                       const int4* __restrict__ meta,
                                       float* __restrict__ out,
                                       int D)
{
    const int r = blockIdx.x;
    const int4 md = meta[r];
    const int start = md.x;
    const int cnt   = md.y;
    const int s     = md.z;
    const float inv = (cnt > 0) ? (1.0f / (float)cnt) : 0.0f;

    for (int d = threadIdx.x; d < D; d += blockDim.x) {
        const float* xp = x + (long long)start * D + d;
        float a0 = 0.f, a1 = 0.f, a2 = 0.f, a3 = 0.f;
        int t = 0;
        for (; t + 4 <= cnt; t += 4) {
            a0 += xp[(long long)(t + 0) * D];
            a1 += xp[(long long)(t + 1) * D];
            a2 += xp[(long long)(t + 2) * D];
            a3 += xp[(long long)(t + 3) * D];
        }
        for (; t < cnt; ++t) a0 += xp[(long long)t * D];
        float sum = (a0 + a1) + (a2 + a3);
        out[(long long)r * D + d] = sum * inv + pe[(long long)s * D + d];
    }
}

// ---------------------------------------------------------------------------
// Launch
// ---------------------------------------------------------------------------
extern "C" void kernel_launch(void* const* d_in, const int* in_sizes, int n_in,
                              void* d_out, int out_size)
{
    const float* x    = (const float*)d_in[0];
    const int*   mask = (const int*)d_in[1];
    const float* pe   = (const float*)d_in[2];

    const int* max_ingr_ptr;
    if (n_in >= 4) {
        max_ingr_ptr = (const int*)d_in[3];
    } else {
        int* p = nullptr;
        cudaGetSymbolAddress((void**)&p, g_fallback_max_ingr);
        max_ingr_ptr = p;
    }

    const int x_size    = in_sizes[0];            // B*L*D
    const int mask_size = in_sizes[1];            // B*L
    const int D         = x_size / mask_size;     // 128
    const int OUT_ROWS  = out_size / D;           // B*max_ingr

    int4* meta_p = nullptr;
    cudaGetSymbolAddress((void**)&meta_p, g_seg_meta);

    if ((D & 3) == 0) {
        const int D4 = D >> 2;
        const int grid = (OUT_ROWS + RPB - 1) / RPB;
        seg_mean_fused_kernel<<<grid, 256>>>(
            (const float4*)x, (const float4*)pe, mask, max_ingr_ptr,
            meta_p, (float4*)d_out, D4, OUT_ROWS, mask_size);
    } else {
        seg_bounds_kernel<<<256, 256>>>(mask, max_ingr_ptr,
                                        mask_size, OUT_ROWS, meta_p);
        seg_mean_scalar_kernel<<<OUT_ROWS, 128>>>(
            x, pe, meta_p, (float*)d_out, D);
    }
}

// round 12
// speedup vs baseline: 1.1158x; 1.1158x over previous
#include <cuda_runtime.h>
#include <cuda_bf16.h>
#include <cstdint>

// ---------------------------------------------------------------------------
// IngredientPositionEncoding: segment-mean pooling + positional encoding.
//
// Kernel 1 (grid-stride over batch rows): warp-shuffle scan of separator
//   mask, emit packed int4 meta per output row (flat_start, cnt, s, 0).
// Kernel 2 (fast path): single-wave, zero-tail static schedule.
//   grid = 512 blocks x 8 warps = 4096 warps; OUT_ROWS = 16384 -> exactly
//   4 rows/warp (warp g does rows g, g+4096, g+8192, g+12288). All per-warp
//   row metas staged to smem by one coalesced 32-thread load at block start
//   (no dependent meta stalls mid-loop). Inner loop = measured-best R3 body.
// ---------------------------------------------------------------------------

#define MAX_SEPS_CAP 4096       // >= L
#define MAX_OUT_ROWS 65536      // >= B*max_ingr
#define NW 8                    // warps per block
#define MAX_ITERS 8             // max rows per warp staged in smem

__device__ int4 g_seg_meta[MAX_OUT_ROWS];
__device__ int  g_fallback_max_ingr = 256;

// ---------------------------------------------------------------------------
// Kernel 1: segment boundaries. Grid-stride over batch rows.
// ---------------------------------------------------------------------------
__global__ void __launch_bounds__(256)
seg_bounds_kernel(const int* __restrict__ mask,
                  const int* __restrict__ max_ingr_ptr,
                  int BL, int OUT_ROWS,
                  int4* __restrict__ meta)
{
    const int max_ingr = *max_ingr_ptr;
    const int B = OUT_ROWS / max_ingr;
    const int L = BL / B;

    __shared__ int sh_sep[MAX_SEPS_CAP];
    __shared__ int sh_warp[9];

    const int tid  = threadIdx.x;
    const int lane = tid & 31;
    const int wid  = tid >> 5;

    for (int b = blockIdx.x; b < B; b += gridDim.x) {
        const int* mrow = mask + b * L;
        const int chunk = (L + 255) / 256;
        const int beg = tid * chunk;
        const int end = min(beg + chunk, L);

        int c = 0;
        if (((chunk & 3) == 0) && ((L & 3) == 0) && (beg < end)) {
            const int4* m4 = (const int4*)(mrow + beg);
            const int n4 = (end - beg) >> 2;
            for (int i = 0; i < n4; ++i) {
                int4 v = m4[i];
                c += (v.x != 0) + (v.y != 0) + (v.z != 0) + (v.w != 0);
            }
        } else {
            for (int i = beg; i < end; ++i) c += (mrow[i] != 0);
        }

        int inc = c;
        #pragma unroll
        for (int o = 1; o < 32; o <<= 1) {
            int v = __shfl_up_sync(0xffffffffu, inc, o);
            if (lane >= o) inc += v;
        }
        if (lane == 31) sh_warp[wid] = inc;
        __syncthreads();

        if (tid == 0) {
            int acc = 0;
            #pragma unroll
            for (int w = 0; w < 8; ++w) { int t = sh_warp[w]; sh_warp[w] = acc; acc += t; }
            sh_warp[8] = acc;
        }
        __syncthreads();

        const int excl = inc - c + sh_warp[wid];
        const int nsep = sh_warp[8];

        int j = excl;
        for (int i = beg; i < end; ++i) {
            if (mrow[i] != 0) {
                if (j < MAX_SEPS_CAP) sh_sep[j] = i;
                ++j;
            }
        }
        __syncthreads();

        for (int s = tid; s < max_ingr; s += 256) {
            int start, cnt;
            if (s < nsep) {
                start = (s == 0) ? 0 : (sh_sep[s - 1] + 1);
                cnt   = sh_sep[s] - start;
            } else if (s == nsep) {
                start = (nsep == 0) ? 0 : (sh_sep[nsep - 1] + 1);
                cnt   = L - start;
            } else {
                start = 0;
                cnt   = 0;
            }
            meta[b * max_ingr + s] = make_int4(b * L + start, cnt, s, 0);
        }
        __syncthreads();
    }
}

// ---------------------------------------------------------------------------
// Kernel 2 (fast path, D % 4 == 0): single-wave zero-tail static schedule.
// Warp g processes rows g + k*WTOT for k in [0, iters). All metas staged
// to smem up front.
// ---------------------------------------------------------------------------
__global__ void __launch_bounds__(NW * 32, 4)
seg_mean_v4_kernel(const float4* __restrict__ x4,
                   const float4* __restrict__ pe4,
                   const int4* __restrict__ meta,
                   float4* __restrict__ out4,
                   int D4, int OUT_ROWS, int iters)
{
    __shared__ int4 sh_meta[NW * MAX_ITERS];

    const int tid  = threadIdx.x;
    const int lane = tid & 31;
    const int w    = tid >> 5;
    const int WTOT = gridDim.x * NW;             // total warps
    const int wbase = blockIdx.x * NW;           // first warp id of this block

    // stage all this block's row metas: t = k*NW + w -> row wbase + w + k*WTOT
    for (int t = tid; t < NW * iters; t += blockDim.x) {
        const int wi = t & (NW - 1);
        const int k  = t / NW;
        const int r  = wbase + wi + k * WTOT;
        if (r < OUT_ROWS) sh_meta[t] = meta[r];
    }
    __syncthreads();

    for (int k = 0; k < iters; ++k) {
        const int r = wbase + w + k * WTOT;
        if (r >= OUT_ROWS) break;
        const int4 md = sh_meta[k * NW + w];
        const int start = md.x;
        const int cnt   = md.y;
        const int s     = md.z;

        const float4* __restrict__ xp = x4 + (long long)start * D4;
        const float inv = (cnt > 0) ? (1.0f / (float)cnt) : 0.0f;

        for (int c = lane; c < D4; c += 32) {
            float4 a0 = {0.f,0.f,0.f,0.f}, a1 = a0, a2 = a0, a3 = a0, a4 = a0;
            int t = 0;
            // 5-deep unroll: cnt=15 -> exactly 3 iterations, no tail
            for (; t + 5 <= cnt; t += 5) {
                float4 v0 = xp[(long long)(t + 0) * D4 + c];
                float4 v1 = xp[(long long)(t + 1) * D4 + c];
                float4 v2 = xp[(long long)(t + 2) * D4 + c];
                float4 v3 = xp[(long long)(t + 3) * D4 + c];
                float4 v4 = xp[(long long)(t + 4) * D4 + c];
                a0.x += v0.x; a0.y += v0.y; a0.z += v0.z; a0.w += v0.w;
                a1.x += v1.x; a1.y += v1.y; a1.z += v1.z; a1.w += v1.w;
                a2.x += v2.x; a2.y += v2.y; a2.z += v2.z; a2.w += v2.w;
                a3.x += v3.x; a3.y += v3.y; a3.z += v3.z; a3.w += v3.w;
                a4.x += v4.x; a4.y += v4.y; a4.z += v4.z; a4.w += v4.w;
            }
            for (; t < cnt; ++t) {
                float4 v = xp[(long long)t * D4 + c];
                a0.x += v.x; a0.y += v.y; a0.z += v.z; a0.w += v.w;
            }
            float4 sum;
            sum.x = ((a0.x + a1.x) + (a2.x + a3.x)) + a4.x;
            sum.y = ((a0.y + a1.y) + (a2.y + a3.y)) + a4.y;
            sum.z = ((a0.z + a1.z) + (a2.z + a3.z)) + a4.z;
            sum.w = ((a0.w + a1.w) + (a2.w + a3.w)) + a4.w;

            float4 p = pe4[(long long)s * D4 + c];
            float4 o;
            o.x = sum.x * inv + p.x;
            o.y = sum.y * inv + p.y;
            o.z = sum.z * inv + p.z;
            o.w = sum.w * inv + p.w;
            out4[(long long)r * D4 + c] = o;
        }
    }
}

// ---------------------------------------------------------------------------
// Kernel 2 (generic fallback, any D): one block per row, thread = channel.
// ---------------------------------------------------------------------------
__global__ void seg_mean_scalar_kernel(const float* __restrict__ x,
                                       const float* __restrict__ pe,
                                       const int4* __restrict__ meta,
                                       float* __restrict__ out,
                                       int D)
{
    const int r = blockIdx.x;
    const int4 md = meta[r];
    const int start = md.x;
    const int cnt   = md.y;
    const int s     = md.z;
    const float inv = (cnt > 0) ? (1.0f / (float)cnt) : 0.0f;

    for (int d = threadIdx.x; d < D; d += blockDim.x) {
        const float* xp = x + (long long)start * D + d;
        float a0 = 0.f, a1 = 0.f, a2 = 0.f, a3 = 0.f;
        int t = 0;
        for (; t + 4 <= cnt; t += 4) {
            a0 += xp[(long long)(t + 0) * D];
            a1 += xp[(long long)(t + 1) * D];
            a2 += xp[(long long)(t + 2) * D];
            a3 += xp[(long long)(t + 3) * D];
        }
        for (; t < cnt; ++t) a0 += xp[(long long)t * D];
        float sum = (a0 + a1) + (a2 + a3);
        out[(long long)r * D + d] = sum * inv + pe[(long long)s * D + d];
    }
}

// ---------------------------------------------------------------------------
// Launch
// ---------------------------------------------------------------------------
extern "C" void kernel_launch(void* const* d_in, const int* in_sizes, int n_in,
                              void* d_out, int out_size)
{
    const float* x    = (const float*)d_in[0];
    const int*   mask = (const int*)d_in[1];
    const float* pe   = (const float*)d_in[2];

    const int* max_ingr_ptr;
    if (n_in >= 4) {
        max_ingr_ptr = (const int*)d_in[3];
    } else {
        int* p = nullptr;
        cudaGetSymbolAddress((void**)&p, g_fallback_max_ingr);
        max_ingr_ptr = p;
    }

    const int x_size    = in_sizes[0];            // B*L*D
    const int mask_size = in_sizes[1];            // B*L
    const int D         = x_size / mask_size;     // 128
    const int OUT_ROWS  = out_size / D;           // B*max_ingr

    int4* meta_p = nullptr;
    cudaGetSymbolAddress((void**)&meta_p, g_seg_meta);

    // Kernel 1: grid-stride over batch rows (B resolved on-device).
    seg_bounds_kernel<<<256, 256>>>(mask, max_ingr_ptr,
                                    mask_size, OUT_ROWS, meta_p);

    if ((D & 3) == 0) {
        const int D4 = D >> 2;
        // pick a single-wave grid (<= 512 blocks = 4096 warps) whose warp
        // count divides OUT_ROWS as evenly as possible; iters <= MAX_ITERS.
        int grid = 512;
        int iters = (OUT_ROWS + grid * NW - 1) / (grid * NW);
        if (iters > MAX_ITERS) {                   // huge inputs: widen grid
            grid = (OUT_ROWS + NW * MAX_ITERS - 1) / (NW * MAX_ITERS);
            iters = MAX_ITERS;
        }
        seg_mean_v4_kernel<<<grid, NW * 32>>>(
            (const float4*)x, (const float4*)pe, meta_p,
            (float4*)d_out, D4, OUT_ROWS, iters);
    } else {
        seg_mean_scalar_kernel<<<OUT_ROWS, 128>>>(
            x, pe, meta_p, (float*)d_out, D);
    }
}

// round 14
// speedup vs baseline: 1.1332x; 1.0156x over previous
#include <cuda_runtime.h>
#include <cuda_bf16.h>
#include <cstdint>

// ---------------------------------------------------------------------------
// IngredientPositionEncoding: segment-mean pooling + positional encoding.
//
// Kernel 1 (grid-stride over batch rows): warp-shuffle scan of separator
//   mask, emit packed int4 meta per output row (flat_start, cnt, s, 0).
// Kernel 2 (fast path): single-wave, zero-tail static schedule.
//   grid = 512 blocks x 8 warps = 4096 warps; OUT_ROWS = 16384 -> exactly
//   4 rows/warp (warp g does rows g, g+4096, g+8192, g+12288). All per-warp
//   row metas staged to smem at block start. Inner loop = measured-best body.
// ---------------------------------------------------------------------------

#define MAX_SEPS_CAP 4096       // >= L
#define MAX_OUT_ROWS 65536      // >= B*max_ingr
#define NW 8                    // warps per block
#define MAX_ITERS 8             // max rows per warp staged in smem

__device__ int4 g_seg_meta[MAX_OUT_ROWS];
__device__ int  g_fallback_max_ingr = 256;

// ---------------------------------------------------------------------------
// Kernel 1: segment boundaries. Grid-stride over batch rows.
// ---------------------------------------------------------------------------
__global__ void __launch_bounds__(256)
seg_bounds_kernel(const int* __restrict__ mask,
                  const int* __restrict__ max_ingr_ptr,
                  int BL, int OUT_ROWS,
                  int4* __restrict__ meta)
{
    const int max_ingr = *max_ingr_ptr;
    const int B = OUT_ROWS / max_ingr;
    const int L = BL / B;

    __shared__ int sh_sep[MAX_SEPS_CAP];
    __shared__ int sh_warp[9];

    const int tid  = threadIdx.x;
    const int lane = tid & 31;
    const int wid  = tid >> 5;

    for (int b = blockIdx.x; b < B; b += gridDim.x) {
        const int* mrow = mask + b * L;
        const int chunk = (L + 255) / 256;
        const int beg = tid * chunk;
        const int end = min(beg + chunk, L);
        const bool vec_ok = ((chunk & 3) == 0) && ((L & 3) == 0) && (beg < end);

        // per-thread separator count (int4 fast path when aligned)
        int c = 0;
        if (vec_ok) {
            const int4* m4 = (const int4*)(mrow + beg);
            const int n4 = (end - beg) >> 2;
            for (int i = 0; i < n4; ++i) {
                int4 v = m4[i];
                c += (v.x != 0) + (v.y != 0) + (v.z != 0) + (v.w != 0);
            }
        } else {
            for (int i = beg; i < end; ++i) c += (mrow[i] != 0);
        }

        // warp inclusive scan
        int inc = c;
        #pragma unroll
        for (int o = 1; o < 32; o <<= 1) {
            int v = __shfl_up_sync(0xffffffffu, inc, o);
            if (lane >= o) inc += v;
        }
        if (lane == 31) sh_warp[wid] = inc;
        __syncthreads();

        if (tid == 0) {
            int acc = 0;
            #pragma unroll
            for (int w = 0; w < 8; ++w) { int t = sh_warp[w]; sh_warp[w] = acc; acc += t; }
            sh_warp[8] = acc;
        }
        __syncthreads();

        const int excl = inc - c + sh_warp[wid];
        const int nsep = sh_warp[8];

        // scatter separator positions (int4 fast path)
        if (vec_ok) {
            int j = excl;
            const int4* m4 = (const int4*)(mrow + beg);
            const int n4 = (end - beg) >> 2;
            for (int i = 0; i < n4; ++i) {
                int4 v = m4[i];
                const int ibase = beg + i * 4;
                if (v.x != 0) { if (j < MAX_SEPS_CAP) sh_sep[j] = ibase + 0; ++j; }
                if (v.y != 0) { if (j < MAX_SEPS_CAP) sh_sep[j] = ibase + 1; ++j; }
                if (v.z != 0) { if (j < MAX_SEPS_CAP) sh_sep[j] = ibase + 2; ++j; }
                if (v.w != 0) { if (j < MAX_SEPS_CAP) sh_sep[j] = ibase + 3; ++j; }
            }
        } else {
            int j = excl;
            for (int i = beg; i < end; ++i) {
                if (mrow[i] != 0) {
                    if (j < MAX_SEPS_CAP) sh_sep[j] = i;
                    ++j;
                }
            }
        }
        __syncthreads();

        for (int s = tid; s < max_ingr; s += 256) {
            int start, cnt;
            if (s < nsep) {
                start = (s == 0) ? 0 : (sh_sep[s - 1] + 1);
                cnt   = sh_sep[s] - start;
            } else if (s == nsep) {
                start = (nsep == 0) ? 0 : (sh_sep[nsep - 1] + 1);
                cnt   = L - start;
            } else {
                start = 0;
                cnt   = 0;
            }
            meta[b * max_ingr + s] = make_int4(b * L + start, cnt, s, 0);
        }
        __syncthreads();
    }
}

// ---------------------------------------------------------------------------
// Kernel 2 (fast path, D % 4 == 0): single-wave zero-tail static schedule.
// Warp g processes rows g + k*WTOT for k in [0, iters). All metas staged
// to smem up front.
// ---------------------------------------------------------------------------
__global__ void __launch_bounds__(NW * 32, 4)
seg_mean_v4_kernel(const float4* __restrict__ x4,
                   const float4* __restrict__ pe4,
                   const int4* __restrict__ meta,
                   float4* __restrict__ out4,
                   int D4, int OUT_ROWS, int iters)
{
    __shared__ int4 sh_meta[NW * MAX_ITERS];

    const int tid  = threadIdx.x;
    const int lane = tid & 31;
    const int w    = tid >> 5;
    const int WTOT = gridDim.x * NW;             // total warps
    const int wbase = blockIdx.x * NW;           // first warp id of this block

    // stage all this block's row metas: t = k*NW + w -> row wbase + w + k*WTOT
    for (int t = tid; t < NW * iters; t += blockDim.x) {
        const int wi = t & (NW - 1);
        const int k  = t / NW;
        const int r  = wbase + wi + k * WTOT;
        if (r < OUT_ROWS) sh_meta[t] = meta[r];
    }
    __syncthreads();

    for (int k = 0; k < iters; ++k) {
        const int r = wbase + w + k * WTOT;
        if (r >= OUT_ROWS) break;
        const int4 md = sh_meta[k * NW + w];
        const int start = md.x;
        const int cnt   = md.y;
        const int s     = md.z;

        const float4* __restrict__ xp = x4 + (long long)start * D4;
        const float inv = (cnt > 0) ? (1.0f / (float)cnt) : 0.0f;

        for (int c = lane; c < D4; c += 32) {
            float4 a0 = {0.f,0.f,0.f,0.f}, a1 = a0, a2 = a0, a3 = a0, a4 = a0;
            int t = 0;
            // 5-deep unroll: cnt=15 -> exactly 3 iterations, no tail
            for (; t + 5 <= cnt; t += 5) {
                float4 v0 = xp[(long long)(t + 0) * D4 + c];
                float4 v1 = xp[(long long)(t + 1) * D4 + c];
                float4 v2 = xp[(long long)(t + 2) * D4 + c];
                float4 v3 = xp[(long long)(t + 3) * D4 + c];
                float4 v4 = xp[(long long)(t + 4) * D4 + c];
                a0.x += v0.x; a0.y += v0.y; a0.z += v0.z; a0.w += v0.w;
                a1.x += v1.x; a1.y += v1.y; a1.z += v1.z; a1.w += v1.w;
                a2.x += v2.x; a2.y += v2.y; a2.z += v2.z; a2.w += v2.w;
                a3.x += v3.x; a3.y += v3.y; a3.z += v3.z; a3.w += v3.w;
                a4.x += v4.x; a4.y += v4.y; a4.z += v4.z; a4.w += v4.w;
            }
            for (; t < cnt; ++t) {
                float4 v = xp[(long long)t * D4 + c];
                a0.x += v.x; a0.y += v.y; a0.z += v.z; a0.w += v.w;
            }
            float4 sum;
            sum.x = ((a0.x + a1.x) + (a2.x + a3.x)) + a4.x;
            sum.y = ((a0.y + a1.y) + (a2.y + a3.y)) + a4.y;
            sum.z = ((a0.z + a1.z) + (a2.z + a3.z)) + a4.z;
            sum.w = ((a0.w + a1.w) + (a2.w + a3.w)) + a4.w;

            float4 p = pe4[(long long)s * D4 + c];
            float4 o;
            o.x = sum.x * inv + p.x;
            o.y = sum.y * inv + p.y;
            o.z = sum.z * inv + p.z;
            o.w = sum.w * inv + p.w;
            out4[(long long)r * D4 + c] = o;
        }
    }
}

// ---------------------------------------------------------------------------
// Kernel 2 (generic fallback, any D): one block per row, thread = channel.
// ---------------------------------------------------------------------------
__global__ void seg_mean_scalar_kernel(const float* __restrict__ x,
                                       const float* __restrict__ pe,
                                       const int4* __restrict__ meta,
                                       float* __restrict__ out,
                                       int D)
{
    const int r = blockIdx.x;
    const int4 md = meta[r];
    const int start = md.x;
    const int cnt   = md.y;
    const int s     = md.z;
    const float inv = (cnt > 0) ? (1.0f / (float)cnt) : 0.0f;

    for (int d = threadIdx.x; d < D; d += blockDim.x) {
        const float* xp = x + (long long)start * D + d;
        float a0 = 0.f, a1 = 0.f, a2 = 0.f, a3 = 0.f;
        int t = 0;
        for (; t + 4 <= cnt; t += 4) {
            a0 += xp[(long long)(t + 0) * D];
            a1 += xp[(long long)(t + 1) * D];
            a2 += xp[(long long)(t + 2) * D];
            a3 += xp[(long long)(t + 3) * D];
        }
        for (; t < cnt; ++t) a0 += xp[(long long)t * D];
        float sum = (a0 + a1) + (a2 + a3);
        out[(long long)r * D + d] = sum * inv + pe[(long long)s * D + d];
    }
}

// ---------------------------------------------------------------------------
// Launch
// ---------------------------------------------------------------------------
extern "C" void kernel_launch(void* const* d_in, const int* in_sizes, int n_in,
                              void* d_out, int out_size)
{
    const float* x    = (const float*)d_in[0];
    const int*   mask = (const int*)d_in[1];
    const float* pe   = (const float*)d_in[2];

    const int* max_ingr_ptr;
    if (n_in >= 4) {
        max_ingr_ptr = (const int*)d_in[3];
    } else {
        int* p = nullptr;
        cudaGetSymbolAddress((void**)&p, g_fallback_max_ingr);
        max_ingr_ptr = p;
    }

    const int x_size    = in_sizes[0];            // B*L*D
    const int mask_size = in_sizes[1];            // B*L
    const int D         = x_size / mask_size;     // 128
    const int OUT_ROWS  = out_size / D;           // B*max_ingr

    int4* meta_p = nullptr;
    cudaGetSymbolAddress((void**)&meta_p, g_seg_meta);

    // Kernel 1: grid-stride over batch rows (B resolved on-device).
    // 64 blocks: covers B=64 in one wave without dead blocks; grid-stride
    // handles larger B generically.
    seg_bounds_kernel<<<64, 256>>>(mask, max_ingr_ptr,
                                   mask_size, OUT_ROWS, meta_p);

    if ((D & 3) == 0) {
        const int D4 = D >> 2;
        // single-wave grid (<= 512 blocks = 4096 warps); iters <= MAX_ITERS.
        int grid = 512;
        int iters = (OUT_ROWS + grid * NW - 1) / (grid * NW);
        if (iters > MAX_ITERS) {                   // huge inputs: widen grid
            grid = (OUT_ROWS + NW * MAX_ITERS - 1) / (NW * MAX_ITERS);
            iters = MAX_ITERS;
        }
        seg_mean_v4_kernel<<<grid, NW * 32>>>(
            (const float4*)x, (const float4*)pe, meta_p,
            (float4*)d_out, D4, OUT_ROWS, iters);
    } else {
        seg_mean_scalar_kernel<<<OUT_ROWS, 128>>>(
            x, pe, meta_p, (float*)d_out, D);
    }
}

// round 15
// speedup vs baseline: 1.1344x; 1.0010x over previous
#include <cuda_runtime.h>
#include <cuda_bf16.h>
#include <cstdint>

// ---------------------------------------------------------------------------
// IngredientPositionEncoding: segment-mean pooling + positional encoding.
//
// Kernel 1 (grid-stride over batch rows): warp-shuffle scan of separator
//   mask, emit packed int4 meta per output row (flat_start, cnt, s, 0).
//   Fires cudaTriggerProgrammaticLaunchCompletion() after its meta writes.
// Kernel 2 (fast path): single-wave, zero-tail static schedule (512 blocks
//   x 8 warps = 4096 warps; 16384 rows -> exactly 4 rows/warp). Launched
//   with PDL so its blocks spin up while k1 drains; cudaGridDependency-
//   Synchronize() before consuming meta. Inner loop = measured-best body.
// ---------------------------------------------------------------------------

#define MAX_SEPS_CAP 4096       // >= L
#define MAX_OUT_ROWS 65536      // >= B*max_ingr
#define NW 8                    // warps per block
#define MAX_ITERS 8             // max rows per warp staged in smem

__device__ int4 g_seg_meta[MAX_OUT_ROWS];
__device__ int  g_fallback_max_ingr = 256;

// ---------------------------------------------------------------------------
// Kernel 1: segment boundaries. Grid-stride over batch rows.
// ---------------------------------------------------------------------------
__global__ void __launch_bounds__(256)
seg_bounds_kernel(const int* __restrict__ mask,
                  const int* __restrict__ max_ingr_ptr,
                  int BL, int OUT_ROWS,
                  int4* __restrict__ meta)
{
    const int max_ingr = *max_ingr_ptr;
    const int B = OUT_ROWS / max_ingr;
    const int L = BL / B;

    __shared__ int sh_sep[MAX_SEPS_CAP];
    __shared__ int sh_warp[9];

    const int tid  = threadIdx.x;
    const int lane = tid & 31;
    const int wid  = tid >> 5;

    for (int b = blockIdx.x; b < B; b += gridDim.x) {
        const int* mrow = mask + b * L;
        const int chunk = (L + 255) / 256;
        const int beg = tid * chunk;
        const int end = min(beg + chunk, L);
        const bool vec_ok = ((chunk & 3) == 0) && ((L & 3) == 0) && (beg < end);

        // per-thread separator count (int4 fast path when aligned)
        int c = 0;
        if (vec_ok) {
            const int4* m4 = (const int4*)(mrow + beg);
            const int n4 = (end - beg) >> 2;
            for (int i = 0; i < n4; ++i) {
                int4 v = m4[i];
                c += (v.x != 0) + (v.y != 0) + (v.z != 0) + (v.w != 0);
            }
        } else {
            for (int i = beg; i < end; ++i) c += (mrow[i] != 0);
        }

        // warp inclusive scan
        int inc = c;
        #pragma unroll
        for (int o = 1; o < 32; o <<= 1) {
            int v = __shfl_up_sync(0xffffffffu, inc, o);
            if (lane >= o) inc += v;
        }
        if (lane == 31) sh_warp[wid] = inc;
        __syncthreads();

        if (tid == 0) {
            int acc = 0;
            #pragma unroll
            for (int w = 0; w < 8; ++w) { int t = sh_warp[w]; sh_warp[w] = acc; acc += t; }
            sh_warp[8] = acc;
        }
        __syncthreads();

        const int excl = inc - c + sh_warp[wid];
        const int nsep = sh_warp[8];

        // scatter separator positions (int4 fast path)
        if (vec_ok) {
            int j = excl;
            const int4* m4 = (const int4*)(mrow + beg);
            const int n4 = (end - beg) >> 2;
            for (int i = 0; i < n4; ++i) {
                int4 v = m4[i];
                const int ibase = beg + i * 4;
                if (v.x != 0) { if (j < MAX_SEPS_CAP) sh_sep[j] = ibase + 0; ++j; }
                if (v.y != 0) { if (j < MAX_SEPS_CAP) sh_sep[j] = ibase + 1; ++j; }
                if (v.z != 0) { if (j < MAX_SEPS_CAP) sh_sep[j] = ibase + 2; ++j; }
                if (v.w != 0) { if (j < MAX_SEPS_CAP) sh_sep[j] = ibase + 3; ++j; }
            }
        } else {
            int j = excl;
            for (int i = beg; i < end; ++i) {
                if (mrow[i] != 0) {
                    if (j < MAX_SEPS_CAP) sh_sep[j] = i;
                    ++j;
                }
            }
        }
        __syncthreads();

        for (int s = tid; s < max_ingr; s += 256) {
            int start, cnt;
            if (s < nsep) {
                start = (s == 0) ? 0 : (sh_sep[s - 1] + 1);
                cnt   = sh_sep[s] - start;
            } else if (s == nsep) {
                start = (nsep == 0) ? 0 : (sh_sep[nsep - 1] + 1);
                cnt   = L - start;
            } else {
                start = 0;
                cnt   = 0;
            }
            meta[b * max_ingr + s] = make_int4(b * L + start, cnt, s, 0);
        }
        __syncthreads();
    }

#if __CUDA_ARCH__ >= 900
    // allow the dependent (streaming) kernel's blocks to launch
    if (tid == 0) cudaTriggerProgrammaticLaunchCompletion();
#endif
}

// ---------------------------------------------------------------------------
// Kernel 2 (fast path, D % 4 == 0): single-wave zero-tail static schedule.
// Warp g processes rows g + k*WTOT for k in [0, iters).
// ---------------------------------------------------------------------------
__global__ void __launch_bounds__(NW * 32, 4)
seg_mean_v4_kernel(const float4* __restrict__ x4,
                   const float4* __restrict__ pe4,
                   const int4* __restrict__ meta,
                   float4* __restrict__ out4,
                   int D4, int OUT_ROWS, int iters)
{
    __shared__ int4 sh_meta[NW * MAX_ITERS];

    const int tid  = threadIdx.x;
    const int lane = tid & 31;
    const int w    = tid >> 5;
    const int WTOT = gridDim.x * NW;             // total warps
    const int wbase = blockIdx.x * NW;           // first warp id of this block

#if __CUDA_ARCH__ >= 900
    // wait for k1 completion (no-op if launched without the PDL attribute)
    cudaGridDependencySynchronize();
#endif

    // stage all this block's row metas: t = k*NW + w -> row wbase + w + k*WTOT
    for (int t = tid; t < NW * iters; t += blockDim.x) {
        const int wi = t & (NW - 1);
        const int k  = t / NW;
        const int r  = wbase + wi + k * WTOT;
        if (r < OUT_ROWS) sh_meta[t] = meta[r];
    }
    __syncthreads();

    for (int k = 0; k < iters; ++k) {
        const int r = wbase + w + k * WTOT;
        if (r >= OUT_ROWS) break;
        const int4 md = sh_meta[k * NW + w];
        const int start = md.x;
        const int cnt   = md.y;
        const int s     = md.z;

        const float4* __restrict__ xp = x4 + (long long)start * D4;
        const float inv = (cnt > 0) ? (1.0f / (float)cnt) : 0.0f;

        for (int c = lane; c < D4; c += 32) {
            float4 a0 = {0.f,0.f,0.f,0.f}, a1 = a0, a2 = a0, a3 = a0, a4 = a0;
            int t = 0;
            // 5-deep unroll: cnt=15 -> exactly 3 iterations, no tail
            for (; t + 5 <= cnt; t += 5) {
                float4 v0 = xp[(long long)(t + 0) * D4 + c];
                float4 v1 = xp[(long long)(t + 1) * D4 + c];
                float4 v2 = xp[(long long)(t + 2) * D4 + c];
                float4 v3 = xp[(long long)(t + 3) * D4 + c];
                float4 v4 = xp[(long long)(t + 4) * D4 + c];
                a0.x += v0.x; a0.y += v0.y; a0.z += v0.z; a0.w += v0.w;
                a1.x += v1.x; a1.y += v1.y; a1.z += v1.z; a1.w += v1.w;
                a2.x += v2.x; a2.y += v2.y; a2.z += v2.z; a2.w += v2.w;
                a3.x += v3.x; a3.y += v3.y; a3.z += v3.z; a3.w += v3.w;
                a4.x += v4.x; a4.y += v4.y; a4.z += v4.z; a4.w += v4.w;
            }
            for (; t < cnt; ++t) {
                float4 v = xp[(long long)t * D4 + c];
                a0.x += v.x; a0.y += v.y; a0.z += v.z; a0.w += v.w;
            }
            float4 sum;
            sum.x = ((a0.x + a1.x) + (a2.x + a3.x)) + a4.x;
            sum.y = ((a0.y + a1.y) + (a2.y + a3.y)) + a4.y;
            sum.z = ((a0.z + a1.z) + (a2.z + a3.z)) + a4.z;
            sum.w = ((a0.w + a1.w) + (a2.w + a3.w)) + a4.w;

            float4 p = pe4[(long long)s * D4 + c];
            float4 o;
            o.x = sum.x * inv + p.x;
            o.y = sum.y * inv + p.y;
            o.z = sum.z * inv + p.z;
            o.w = sum.w * inv + p.w;
            out4[(long long)r * D4 + c] = o;
        }
    }
}

// ---------------------------------------------------------------------------
// Kernel 2 (generic fallback, any D): one block per row, thread = channel.
// ---------------------------------------------------------------------------
__global__ void seg_mean_scalar_kernel(const float* __restrict__ x,
                                       const float* __restrict__ pe,
                                       const int4* __restrict__ meta,
                                       float* __restrict__ out,
                                       int D)
{
    const int r = blockIdx.x;
    const int4 md = meta[r];
    const int start = md.x;
    const int cnt   = md.y;
    const int s     = md.z;
    const float inv = (cnt > 0) ? (1.0f / (float)cnt) : 0.0f;

    for (int d = threadIdx.x; d < D; d += blockDim.x) {
        const float* xp = x + (long long)start * D + d;
        float a0 = 0.f, a1 = 0.f, a2 = 0.f, a3 = 0.f;
        int t = 0;
        for (; t + 4 <= cnt; t += 4) {
            a0 += xp[(long long)(t + 0) * D];
            a1 += xp[(long long)(t + 1) * D];
            a2 += xp[(long long)(t + 2) * D];
            a3 += xp[(long long)(t + 3) * D];
        }
        for (; t < cnt; ++t) a0 += xp[(long long)t * D];
        float sum = (a0 + a1) + (a2 + a3);
        out[(long long)r * D + d] = sum * inv + pe[(long long)s * D + d];
    }
}

// ---------------------------------------------------------------------------
// Launch
// ---------------------------------------------------------------------------
extern "C" void kernel_launch(void* const* d_in, const int* in_sizes, int n_in,
                              void* d_out, int out_size)
{
    const float* x    = (const float*)d_in[0];
    const int*   mask = (const int*)d_in[1];
    const float* pe   = (const float*)d_in[2];

    const int* max_ingr_ptr;
    if (n_in >= 4) {
        max_ingr_ptr = (const int*)d_in[3];
    } else {
        int* p = nullptr;
        cudaGetSymbolAddress((void**)&p, g_fallback_max_ingr);
        max_ingr_ptr = p;
    }

    const int x_size    = in_sizes[0];            // B*L*D
    const int mask_size = in_sizes[1];            // B*L
    const int D         = x_size / mask_size;     // 128
    const int OUT_ROWS  = out_size / D;           // B*max_ingr

    int4* meta_p = nullptr;
    cudaGetSymbolAddress((void**)&meta_p, g_seg_meta);

    // Kernel 1: 64 blocks (covers B=64 in one wave; grid-stride for larger B)
    seg_bounds_kernel<<<64, 256>>>(mask, max_ingr_ptr,
                                   mask_size, OUT_ROWS, meta_p);

    if ((D & 3) == 0) {
        const int D4 = D >> 2;
        int grid = 512;
        int iters = (OUT_ROWS + grid * NW - 1) / (grid * NW);
        if (iters > MAX_ITERS) {                   // huge inputs: widen grid
            grid = (OUT_ROWS + NW * MAX_ITERS - 1) / (NW * MAX_ITERS);
            iters = MAX_ITERS;
        }

        // PDL launch: k2's blocks spin up while k1 drains.
        cudaLaunchConfig_t cfg = {};
        cfg.gridDim  = dim3((unsigned)grid, 1, 1);
        cfg.blockDim = dim3(NW * 32, 1, 1);
        cfg.dynamicSmemBytes = 0;
        cfg.stream = 0;
        cudaLaunchAttribute attrs[1];
        attrs[0].id = cudaLaunchAttributeProgrammaticStreamSerialization;
        attrs[0].val.programmaticStreamSerializationAllowed = 1;
        cfg.attrs = attrs;
        cfg.numAttrs = 1;

        cudaError_t err = cudaLaunchKernelEx(
            &cfg, seg_mean_v4_kernel,
            (const float4*)x, (const float4*)pe, (const int4*)meta_p,
            (float4*)d_out, D4, OUT_ROWS, iters);
        if (err != cudaSuccess) {
            // fallback: plain launch (grid sync is a no-op without PDL attr)
            seg_mean_v4_kernel<<<grid, NW * 32>>>(
                (const float4*)x, (const float4*)pe, meta_p,
                (float4*)d_out, D4, OUT_ROWS, iters);
        }
    } else {
        seg_mean_scalar_kernel<<<OUT_ROWS, 128>>>(
            x, pe, meta_p, (float*)d_out, D);
    }
}

// round 16
// speedup vs baseline: 1.1499x; 1.0137x over previous
#include <cuda_runtime.h>
#include <cuda_bf16.h>
#include <cstdint>

// ---------------------------------------------------------------------------
// IngredientPositionEncoding: segment-mean pooling + positional encoding.
//
// Kernel 1 (512 threads/block, grid-stride over batch rows): single-pass
//   warp-shuffle scan of separator mask (values kept in registers between
//   count and scatter), emit packed int4 meta (flat_start, cnt, s, 0).
//   Triggers PDL completion when done.
// Kernel 2 (fast path): single-wave, zero-tail static schedule (512 blocks
//   x 8 warps = 4096 warps; 16384 rows -> exactly 4 rows/warp), launched
//   with PDL; measured-best 5-deep float4 streaming body.
// ---------------------------------------------------------------------------

#define MAX_SEPS_CAP 4096       // >= L
#define MAX_OUT_ROWS 65536      // >= B*max_ingr
#define NW 8                    // k2 warps per block
#define MAX_ITERS 8             // max rows per warp staged in smem
#define K1_NTH 512              // k1 threads per block

__device__ int4 g_seg_meta[MAX_OUT_ROWS];
__device__ int  g_fallback_max_ingr = 256;

// ---------------------------------------------------------------------------
// Kernel 1: segment boundaries. Grid-stride over batch rows.
// ---------------------------------------------------------------------------
__global__ void __launch_bounds__(K1_NTH)
seg_bounds_kernel(const int* __restrict__ mask,
                  const int* __restrict__ max_ingr_ptr,
                  int BL, int OUT_ROWS,
                  int4* __restrict__ meta)
{
    const int max_ingr = *max_ingr_ptr;
    const int B = OUT_ROWS / max_ingr;
    const int L = BL / B;

    __shared__ int sh_sep[MAX_SEPS_CAP];
    __shared__ int sh_warp[(K1_NTH / 32) + 1];

    const int tid  = threadIdx.x;
    const int lane = tid & 31;
    const int wid  = tid >> 5;
    const int NWRP = K1_NTH / 32;

    for (int b = blockIdx.x; b < B; b += gridDim.x) {
        const int* mrow = mask + b * L;
        const int chunk = (L + K1_NTH - 1) / K1_NTH;
        const int beg = tid * chunk;
        const int end = min(beg + chunk, L);
        // fast path: chunk == 8 and aligned (covers L % (4*K1_NTH) == 0)
        const bool vec_ok = (chunk == 8) && ((L & 7) == 0) && (beg + 8 <= L);

        int4 va, vb;            // registers reused for scatter (no re-read)
        int c = 0;
        if (vec_ok) {
            const int4* m4 = (const int4*)(mrow + beg);
            va = m4[0];
            vb = m4[1];
            c  = (va.x != 0) + (va.y != 0) + (va.z != 0) + (va.w != 0)
               + (vb.x != 0) + (vb.y != 0) + (vb.z != 0) + (vb.w != 0);
        } else {
            for (int i = beg; i < end; ++i) c += (mrow[i] != 0);
        }

        // warp inclusive scan
        int inc = c;
        #pragma unroll
        for (int o = 1; o < 32; o <<= 1) {
            int v = __shfl_up_sync(0xffffffffu, inc, o);
            if (lane >= o) inc += v;
        }
        if (lane == 31) sh_warp[wid] = inc;
        __syncthreads();

        if (tid == 0) {
            int acc = 0;
            #pragma unroll
            for (int w = 0; w < NWRP; ++w) { int t = sh_warp[w]; sh_warp[w] = acc; acc += t; }
            sh_warp[NWRP] = acc;
        }
        __syncthreads();

        const int excl = inc - c + sh_warp[wid];
        const int nsep = sh_warp[NWRP];

        // scatter separator positions from the registers loaded above
        if (vec_ok) {
            int j = excl;
            if (va.x != 0) { if (j < MAX_SEPS_CAP) sh_sep[j] = beg + 0; ++j; }
            if (va.y != 0) { if (j < MAX_SEPS_CAP) sh_sep[j] = beg + 1; ++j; }
            if (va.z != 0) { if (j < MAX_SEPS_CAP) sh_sep[j] = beg + 2; ++j; }
            if (va.w != 0) { if (j < MAX_SEPS_CAP) sh_sep[j] = beg + 3; ++j; }
            if (vb.x != 0) { if (j < MAX_SEPS_CAP) sh_sep[j] = beg + 4; ++j; }
            if (vb.y != 0) { if (j < MAX_SEPS_CAP) sh_sep[j] = beg + 5; ++j; }
            if (vb.z != 0) { if (j < MAX_SEPS_CAP) sh_sep[j] = beg + 6; ++j; }
            if (vb.w != 0) { if (j < MAX_SEPS_CAP) sh_sep[j] = beg + 7; ++j; }
        } else {
            int j = excl;
            for (int i = beg; i < end; ++i) {
                if (mrow[i] != 0) {
                    if (j < MAX_SEPS_CAP) sh_sep[j] = i;
                    ++j;
                }
            }
        }
        __syncthreads();

        for (int s = tid; s < max_ingr; s += K1_NTH) {
            int start, cnt;
            if (s < nsep) {
                start = (s == 0) ? 0 : (sh_sep[s - 1] + 1);
                cnt   = sh_sep[s] - start;
            } else if (s == nsep) {
                start = (nsep == 0) ? 0 : (sh_sep[nsep - 1] + 1);
                cnt   = L - start;
            } else {
                start = 0;
                cnt   = 0;
            }
            meta[b * max_ingr + s] = make_int4(b * L + start, cnt, s, 0);
        }
        __syncthreads();
    }

#if __CUDA_ARCH__ >= 900
    if (tid == 0) cudaTriggerProgrammaticLaunchCompletion();
#endif
}

// ---------------------------------------------------------------------------
// Kernel 2 (fast path, D % 4 == 0): single-wave zero-tail static schedule.
// ---------------------------------------------------------------------------
__global__ void __launch_bounds__(NW * 32, 4)
seg_mean_v4_kernel(const float4* __restrict__ x4,
                   const float4* __restrict__ pe4,
                   const int4* __restrict__ meta,
                   float4* __restrict__ out4,
                   int D4, int OUT_ROWS, int iters)
{
    __shared__ int4 sh_meta[NW * MAX_ITERS];

    const int tid  = threadIdx.x;
    const int lane = tid & 31;
    const int w    = tid >> 5;
    const int WTOT = gridDim.x * NW;
    const int wbase = blockIdx.x * NW;

#if __CUDA_ARCH__ >= 900
    cudaGridDependencySynchronize();
#endif

    for (int t = tid; t < NW * iters; t += blockDim.x) {
        const int wi = t & (NW - 1);
        const int k  = t / NW;
        const int r  = wbase + wi + k * WTOT;
        if (r < OUT_ROWS) sh_meta[t] = meta[r];
    }
    __syncthreads();

    for (int k = 0; k < iters; ++k) {
        const int r = wbase + w + k * WTOT;
        if (r >= OUT_ROWS) break;
        const int4 md = sh_meta[k * NW + w];
        const int start = md.x;
        const int cnt   = md.y;
        const int s     = md.z;

        const float4* __restrict__ xp = x4 + (long long)start * D4;
        const float inv = (cnt > 0) ? (1.0f / (float)cnt) : 0.0f;

        for (int c = lane; c < D4; c += 32) {
            float4 a0 = {0.f,0.f,0.f,0.f}, a1 = a0, a2 = a0, a3 = a0, a4 = a0;
            int t = 0;
            for (; t + 5 <= cnt; t += 5) {
                float4 v0 = xp[(long long)(t + 0) * D4 + c];
                float4 v1 = xp[(long long)(t + 1) * D4 + c];
                float4 v2 = xp[(long long)(t + 2) * D4 + c];
                float4 v3 = xp[(long long)(t + 3) * D4 + c];
                float4 v4 = xp[(long long)(t + 4) * D4 + c];
                a0.x += v0.x; a0.y += v0.y; a0.z += v0.z; a0.w += v0.w;
                a1.x += v1.x; a1.y += v1.y; a1.z += v1.z; a1.w += v1.w;
                a2.x += v2.x; a2.y += v2.y; a2.z += v2.z; a2.w += v2.w;
                a3.x += v3.x; a3.y += v3.y; a3.z += v3.z; a3.w += v3.w;
                a4.x += v4.x; a4.y += v4.y; a4.z += v4.z; a4.w += v4.w;
            }
            for (; t < cnt; ++t) {
                float4 v = xp[(long long)t * D4 + c];
                a0.x += v.x; a0.y += v.y; a0.z += v.z; a0.w += v.w;
            }
            float4 sum;
            sum.x = ((a0.x + a1.x) + (a2.x + a3.x)) + a4.x;
            sum.y = ((a0.y + a1.y) + (a2.y + a3.y)) + a4.y;
            sum.z = ((a0.z + a1.z) + (a2.z + a3.z)) + a4.z;
            sum.w = ((a0.w + a1.w) + (a2.w + a3.w)) + a4.w;

            float4 p = pe4[(long long)s * D4 + c];
            float4 o;
            o.x = sum.x * inv + p.x;
            o.y = sum.y * inv + p.y;
            o.z = sum.z * inv + p.z;
            o.w = sum.w * inv + p.w;
            out4[(long long)r * D4 + c] = o;
        }
    }
}

// ---------------------------------------------------------------------------
// Kernel 2 (generic fallback, any D): one block per row, thread = channel.
// ---------------------------------------------------------------------------
__global__ void seg_mean_scalar_kernel(const float* __restrict__ x,
                                       const float* __restrict__ pe,
                                       const int4* __restrict__ meta,
                                       float* __restrict__ out,
                                       int D)
{
    const int r = blockIdx.x;
    const int4 md = meta[r];
    const int start = md.x;
    const int cnt   = md.y;
    const int s     = md.z;
    const float inv = (cnt > 0) ? (1.0f / (float)cnt) : 0.0f;

    for (int d = threadIdx.x; d < D; d += blockDim.x) {
        const float* xp = x + (long long)start * D + d;
        float a0 = 0.f, a1 = 0.f, a2 = 0.f, a3 = 0.f;
        int t = 0;
        for (; t + 4 <= cnt; t += 4) {
            a0 += xp[(long long)(t + 0) * D];
            a1 += xp[(long long)(t + 1) * D];
            a2 += xp[(long long)(t + 2) * D];
            a3 += xp[(long long)(t + 3) * D];
        }
        for (; t < cnt; ++t) a0 += xp[(long long)t * D];
        float sum = (a0 + a1) + (a2 + a3);
        out[(long long)r * D + d] = sum * inv + pe[(long long)s * D + d];
    }
}

// ---------------------------------------------------------------------------
// Launch
// ---------------------------------------------------------------------------
extern "C" void kernel_launch(void* const* d_in, const int* in_sizes, int n_in,
                              void* d_out, int out_size)
{
    const float* x    = (const float*)d_in[0];
    const int*   mask = (const int*)d_in[1];
    const float* pe   = (const float*)d_in[2];

    const int* max_ingr_ptr;
    if (n_in >= 4) {
        max_ingr_ptr = (const int*)d_in[3];
    } else {
        int* p = nullptr;
        cudaGetSymbolAddress((void**)&p, g_fallback_max_ingr);
        max_ingr_ptr = p;
    }

    const int x_size    = in_sizes[0];            // B*L*D
    const int mask_size = in_sizes[1];            // B*L
    const int D         = x_size / mask_size;     // 128
    const int OUT_ROWS  = out_size / D;           // B*max_ingr

    int4* meta_p = nullptr;
    cudaGetSymbolAddress((void**)&meta_p, g_seg_meta);

    // Kernel 1: 64 blocks x 512 threads (covers B=64 in one wave).
    seg_bounds_kernel<<<64, K1_NTH>>>(mask, max_ingr_ptr,
                                      mask_size, OUT_ROWS, meta_p);

    if ((D & 3) == 0) {
        const int D4 = D >> 2;
        int grid = 512;
        int iters = (OUT_ROWS + grid * NW - 1) / (grid * NW);
        if (iters > MAX_ITERS) {
            grid = (OUT_ROWS + NW * MAX_ITERS - 1) / (NW * MAX_ITERS);
            iters = MAX_ITERS;
        }

        cudaLaunchConfig_t cfg = {};
        cfg.gridDim  = dim3((unsigned)grid, 1, 1);
        cfg.blockDim = dim3(NW * 32, 1, 1);
        cfg.dynamicSmemBytes = 0;
        cfg.stream = 0;
        cudaLaunchAttribute attrs[1];
        attrs[0].id = cudaLaunchAttributeProgrammaticStreamSerialization;
        attrs[0].val.programmaticStreamSerializationAllowed = 1;
        cfg.attrs = attrs;
        cfg.numAttrs = 1;

        cudaError_t err = cudaLaunchKernelEx(
            &cfg, seg_mean_v4_kernel,
            (const float4*)x, (const float4*)pe, (const int4*)meta_p,
            (float4*)d_out, D4, OUT_ROWS, iters);
        if (err != cudaSuccess) {
            seg_mean_v4_kernel<<<grid, NW * 32>>>(
                (const float4*)x, (const float4*)pe, meta_p,
                (float4*)d_out, D4, OUT_ROWS, iters);
        }
    } else {
        seg_mean_scalar_kernel<<<OUT_ROWS, 128>>>(
            x, pe, meta_p, (float*)d_out, D);
    }
}

// round 17
// speedup vs baseline: 1.1735x; 1.0205x over previous
#include <cuda_runtime.h>
#include <cuda_bf16.h>
#include <cstdint>

// ---------------------------------------------------------------------------
// IngredientPositionEncoding: segment-mean pooling + positional encoding.
//
// Kernel 1 (512 threads/block, grid-stride over batch rows): single-pass
//   warp-shuffle scan of separator mask (values kept in registers between
//   count and scatter), emit packed int4 meta (flat_start, cnt, s, 0).
//   Triggers PDL completion when done.
// Kernel 2 (fast path): single-wave, zero-tail static schedule (512 blocks
//   x 8 warps = 4096 warps; 16384 rows -> exactly 4 rows/warp), launched
//   with PDL; measured-best 5-deep float4 streaming body.
// ---------------------------------------------------------------------------

#define MAX_SEPS_CAP 4096       // >= L
#define MAX_OUT_ROWS 65536      // >= B*max_ingr
#define NW 8                    // k2 warps per block
#define MAX_ITERS 8             // max rows per warp staged in smem
#define K1_NTH 512              // k1 threads per block

__device__ int4 g_seg_meta[MAX_OUT_ROWS];
__device__ int  g_fallback_max_ingr = 256;

// ---------------------------------------------------------------------------
// Kernel 1: segment boundaries. Grid-stride over batch rows.
// ---------------------------------------------------------------------------
__global__ void __launch_bounds__(K1_NTH)
seg_bounds_kernel(const int* __restrict__ mask,
                  const int* __restrict__ max_ingr_ptr,
                  int BL, int OUT_ROWS,
                  int4* __restrict__ meta)
{
    const int max_ingr = *max_ingr_ptr;
    const int B = OUT_ROWS / max_ingr;
    const int L = BL / B;

    __shared__ int sh_sep[MAX_SEPS_CAP];
    __shared__ int sh_warp[(K1_NTH / 32) + 1];

    const int tid  = threadIdx.x;
    const int lane = tid & 31;
    const int wid  = tid >> 5;
    const int NWRP = K1_NTH / 32;

    for (int b = blockIdx.x; b < B; b += gridDim.x) {
        const int* mrow = mask + b * L;
        const int chunk = (L + K1_NTH - 1) / K1_NTH;
        const int beg = tid * chunk;
        const int end = min(beg + chunk, L);
        // fast path: chunk == 8 and aligned (covers L % (4*K1_NTH) == 0)
        const bool vec_ok = (chunk == 8) && ((L & 7) == 0) && (beg + 8 <= L);

        int4 va, vb;            // registers reused for scatter (no re-read)
        int c = 0;
        if (vec_ok) {
            const int4* m4 = (const int4*)(mrow + beg);
            va = m4[0];
            vb = m4[1];
            c  = (va.x != 0) + (va.y != 0) + (va.z != 0) + (va.w != 0)
               + (vb.x != 0) + (vb.y != 0) + (vb.z != 0) + (vb.w != 0);
        } else {
            for (int i = beg; i < end; ++i) c += (mrow[i] != 0);
        }

        // warp inclusive scan
        int inc = c;
        #pragma unroll
        for (int o = 1; o < 32; o <<= 1) {
            int v = __shfl_up_sync(0xffffffffu, inc, o);
            if (lane >= o) inc += v;
        }
        if (lane == 31) sh_warp[wid] = inc;
        __syncthreads();

        if (tid == 0) {
            int acc = 0;
            #pragma unroll
            for (int w = 0; w < NWRP; ++w) { int t = sh_warp[w]; sh_warp[w] = acc; acc += t; }
            sh_warp[NWRP] = acc;
        }
        __syncthreads();

        const int excl = inc - c + sh_warp[wid];
        const int nsep = sh_warp[NWRP];

        // scatter separator positions from the registers loaded above
        if (vec_ok) {
            int j = excl;
            if (va.x != 0) { if (j < MAX_SEPS_CAP) sh_sep[j] = beg + 0; ++j; }
            if (va.y != 0) { if (j < MAX_SEPS_CAP) sh_sep[j] = beg + 1; ++j; }
            if (va.z != 0) { if (j < MAX_SEPS_CAP) sh_sep[j] = beg + 2; ++j; }
            if (va.w != 0) { if (j < MAX_SEPS_CAP) sh_sep[j] = beg + 3; ++j; }
            if (vb.x != 0) { if (j < MAX_SEPS_CAP) sh_sep[j] = beg + 4; ++j; }
            if (vb.y != 0) { if (j < MAX_SEPS_CAP) sh_sep[j] = beg + 5; ++j; }
            if (vb.z != 0) { if (j < MAX_SEPS_CAP) sh_sep[j] = beg + 6; ++j; }
            if (vb.w != 0) { if (j < MAX_SEPS_CAP) sh_sep[j] = beg + 7; ++j; }
        } else {
            int j = excl;
            for (int i = beg; i < end; ++i) {
                if (mrow[i] != 0) {
                    if (j < MAX_SEPS_CAP) sh_sep[j] = i;
                    ++j;
                }
            }
        }
        __syncthreads();

        for (int s = tid; s < max_ingr; s += K1_NTH) {
            int start, cnt;
            if (s < nsep) {
                start = (s == 0) ? 0 : (sh_sep[s - 1] + 1);
                cnt   = sh_sep[s] - start;
            } else if (s == nsep) {
                start = (nsep == 0) ? 0 : (sh_sep[nsep - 1] + 1);
                cnt   = L - start;
            } else {
                start = 0;
                cnt   = 0;
            }
            meta[b * max_ingr + s] = make_int4(b * L + start, cnt, s, 0);
        }
        __syncthreads();
    }

#if __CUDA_ARCH__ >= 900
    if (tid == 0) cudaTriggerProgrammaticLaunchCompletion();
#endif
}

// ---------------------------------------------------------------------------
// Kernel 2 (fast path, D % 4 == 0): single-wave zero-tail static schedule.
// ---------------------------------------------------------------------------
__global__ void __launch_bounds__(NW * 32, 4)
seg_mean_v4_kernel(const float4* __restrict__ x4,
                   const float4* __restrict__ pe4,
                   const int4* __restrict__ meta,
                   float4* __restrict__ out4,
                   int D4, int OUT_ROWS, int iters)
{
    __shared__ int4 sh_meta[NW * MAX_ITERS];

    const int tid  = threadIdx.x;
    const int lane = tid & 31;
    const int w    = tid >> 5;
    const int WTOT = gridDim.x * NW;
    const int wbase = blockIdx.x * NW;

#if __CUDA_ARCH__ >= 900
    cudaGridDependencySynchronize();
#endif

    for (int t = tid; t < NW * iters; t += blockDim.x) {
        const int wi = t & (NW - 1);
        const int k  = t / NW;
        const int r  = wbase + wi + k * WTOT;
        if (r < OUT_ROWS) sh_meta[t] = meta[r];
    }
    __syncthreads();

    for (int k = 0; k < iters; ++k) {
        const int r = wbase + w + k * WTOT;
        if (r >= OUT_ROWS) break;
        const int4 md = sh_meta[k * NW + w];
        const int start = md.x;
        const int cnt   = md.y;
        const int s     = md.z;

        const float4* __restrict__ xp = x4 + (long long)start * D4;
        const float inv = (cnt > 0) ? (1.0f / (float)cnt) : 0.0f;

        for (int c = lane; c < D4; c += 32) {
            float4 a0 = {0.f,0.f,0.f,0.f}, a1 = a0, a2 = a0, a3 = a0, a4 = a0;
            int t = 0;
            for (; t + 5 <= cnt; t += 5) {
                float4 v0 = xp[(long long)(t + 0) * D4 + c];
                float4 v1 = xp[(long long)(t + 1) * D4 + c];
                float4 v2 = xp[(long long)(t + 2) * D4 + c];
                float4 v3 = xp[(long long)(t + 3) * D4 + c];
                float4 v4 = xp[(long long)(t + 4) * D4 + c];
                a0.x += v0.x; a0.y += v0.y; a0.z += v0.z; a0.w += v0.w;
                a1.x += v1.x; a1.y += v1.y; a1.z += v1.z; a1.w += v1.w;
                a2.x += v2.x; a2.y += v2.y; a2.z += v2.z; a2.w += v2.w;
                a3.x += v3.x; a3.y += v3.y; a3.z += v3.z; a3.w += v3.w;
                a4.x += v4.x; a4.y += v4.y; a4.z += v4.z; a4.w += v4.w;
            }
            for (; t < cnt; ++t) {
                float4 v = xp[(long long)t * D4 + c];
                a0.x += v.x; a0.y += v.y; a0.z += v.z; a0.w += v.w;
            }
            float4 sum;
            sum.x = ((a0.x + a1.x) + (a2.x + a3.x)) + a4.x;
            sum.y = ((a0.y + a1.y) + (a2.y + a3.y)) + a4.y;
            sum.z = ((a0.z + a1.z) + (a2.z + a3.z)) + a4.z;
            sum.w = ((a0.w + a1.w) + (a2.w + a3.w)) + a4.w;

            float4 p = pe4[(long long)s * D4 + c];
            float4 o;
            o.x = sum.x * inv + p.x;
            o.y = sum.y * inv + p.y;
            o.z = sum.z * inv + p.z;
            o.w = sum.w * inv + p.w;
            out4[(long long)r * D4 + c] = o;
        }
    }
}

// ---------------------------------------------------------------------------
// Kernel 2 (generic fallback, any D): one block per row, thread = channel.
// ---------------------------------------------------------------------------
__global__ void seg_mean_scalar_kernel(const float* __restrict__ x,
                                       const float* __restrict__ pe,
                                       const int4* __restrict__ meta,
                                       float* __restrict__ out,
                                       int D)
{
    const int r = blockIdx.x;
    const int4 md = meta[r];
    const int start = md.x;
    const int cnt   = md.y;
    const int s     = md.z;
    const float inv = (cnt > 0) ? (1.0f / (float)cnt) : 0.0f;

    for (int d = threadIdx.x; d < D; d += blockDim.x) {
        const float* xp = x + (long long)start * D + d;
        float a0 = 0.f, a1 = 0.f, a2 = 0.f, a3 = 0.f;
        int t = 0;
        for (; t + 4 <= cnt; t += 4) {
            a0 += xp[(long long)(t + 0) * D];
            a1 += xp[(long long)(t + 1) * D];
            a2 += xp[(long long)(t + 2) * D];
            a3 += xp[(long long)(t + 3) * D];
        }
        for (; t < cnt; ++t) a0 += xp[(long long)t * D];
        float sum = (a0 + a1) + (a2 + a3);
        out[(long long)r * D + d] = sum * inv + pe[(long long)s * D + d];
    }
}

// ---------------------------------------------------------------------------
// Launch
// ---------------------------------------------------------------------------
extern "C" void kernel_launch(void* const* d_in, const int* in_sizes, int n_in,
                              void* d_out, int out_size)
{
    const float* x    = (const float*)d_in[0];
    const int*   mask = (const int*)d_in[1];
    const float* pe   = (const float*)d_in[2];

    const int* max_ingr_ptr;
    if (n_in >= 4) {
        max_ingr_ptr = (const int*)d_in[3];
    } else {
        int* p = nullptr;
        cudaGetSymbolAddress((void**)&p, g_fallback_max_ingr);
        max_ingr_ptr = p;
    }

    const int x_size    = in_sizes[0];            // B*L*D
    const int mask_size = in_sizes[1];            // B*L
    const int D         = x_size / mask_size;     // 128
    const int OUT_ROWS  = out_size / D;           // B*max_ingr

    int4* meta_p = nullptr;
    cudaGetSymbolAddress((void**)&meta_p, g_seg_meta);

    // Kernel 1: 64 blocks x 512 threads (covers B=64 in one wave).
    seg_bounds_kernel<<<64, K1_NTH>>>(mask, max_ingr_ptr,
                                      mask_size, OUT_ROWS, meta_p);

    if ((D & 3) == 0) {
        const int D4 = D >> 2;
        int grid = 512;
        int iters = (OUT_ROWS + grid * NW - 1) / (grid * NW);
        if (iters > MAX_ITERS) {
            grid = (OUT_ROWS + NW * MAX_ITERS - 1) / (NW * MAX_ITERS);
            iters = MAX_ITERS;
        }

        cudaLaunchConfig_t cfg = {};
        cfg.gridDim  = dim3((unsigned)grid, 1, 1);
        cfg.blockDim = dim3(NW * 32, 1, 1);
        cfg.dynamicSmemBytes = 0;
        cfg.stream = 0;
        cudaLaunchAttribute attrs[1];
        attrs[0].id = cudaLaunchAttributeProgrammaticStreamSerialization;
        attrs[0].val.programmaticStreamSerializationAllowed = 1;
        cfg.attrs = attrs;
        cfg.numAttrs = 1;

        cudaError_t err = cudaLaunchKernelEx(
            &cfg, seg_mean_v4_kernel,
            (const float4*)x, (const float4*)pe, (const int4*)meta_p,
            (float4*)d_out, D4, OUT_ROWS, iters);
        if (err != cudaSuccess) {
            seg_mean_v4_kernel<<<grid, NW * 32>>>(
                (const float4*)x, (const float4*)pe, meta_p,
                (float4*)d_out, D4, OUT_ROWS, iters);
        }
    } else {
        seg_mean_scalar_kernel<<<OUT_ROWS, 128>>>(
            x, pe, meta_p, (float*)d_out, D);
    }
}